// round 6
// baseline (speedup 1.0000x reference)
#include <cuda_runtime.h>
#include <cuda_bf16.h>
#include <math.h>
#include <stdint.h>

// ---------------- problem constants ----------------
#define BBATCH 4
#define LL 4096
#define DD 1024
#define MM (BBATCH * LL)          // 16384 rows
#define NCHUNK 64
#define TCHUNK (LL / NCHUNK)      // 64
#define TOTN (BBATCH * NCHUNK * DD)

// ---------------- fp32 scratch ----------------
__device__ float g_pv[(size_t)MM * DD];
__device__ float g_kc[(size_t)MM * DD];
__device__ float g_ks[(size_t)MM * DD];
__device__ float g_kv[(size_t)MM * DD];
__device__ float g_gh[(size_t)MM * DD];
__device__ float g_bh[(size_t)MM * (DD / 2)];
__device__ float g_vg[MM];
__device__ float g_gcs[MM];
__device__ float g_bw[MM * 2];
__device__ float g_mpc[(size_t)MM * DD];
__device__ float g_mps[(size_t)MM * DD];
__device__ float g_mkc[(size_t)MM * DD];
__device__ float g_mks[(size_t)MM * DD];
__device__ float g_tot[4 * TOTN];
__device__ float g_blend[(size_t)MM * DD];

// ---------------- bf16 split-triple scratch ----------------
// A-side triple per k: (hi, lo, hi). B-side [N][3K] triple: (hi, hi, lo).
__device__ __nv_bfloat16 g_x3 [(size_t)MM * 3 * DD];
__device__ __nv_bfloat16 g_xc3[(size_t)MM * 6 * DD];
__device__ __nv_bfloat16 g_ln3[(size_t)MM * 3 * DD];
__device__ __nv_bfloat16 g_Wpv3[(size_t)3 * DD * DD];
__device__ __nv_bfloat16 g_Wk3 [(size_t)3 * DD * DD];
__device__ __nv_bfloat16 g_Wkv3[(size_t)3 * DD * DD];
__device__ __nv_bfloat16 g_Wg13[(size_t)6 * DD * DD];
__device__ __nv_bfloat16 g_Wb13[(size_t)3 * DD * (DD / 2)];
__device__ __nv_bfloat16 g_Wo3 [(size_t)3 * DD * DD];

// ================= PTX helpers (family-safe: no sm_103a-only ops) =================
__device__ __forceinline__ uint32_t s2u(const void* p) {
    return (uint32_t)__cvta_generic_to_shared(p);
}
__device__ __forceinline__ void ldsm4(uint32_t& r0, uint32_t& r1, uint32_t& r2, uint32_t& r3, uint32_t a) {
    asm volatile("ldmatrix.sync.aligned.m8n8.x4.shared.b16 {%0,%1,%2,%3}, [%4];"
                 : "=r"(r0), "=r"(r1), "=r"(r2), "=r"(r3) : "r"(a));
}
__device__ __forceinline__ void mma16816(float* d, const uint32_t* a, uint32_t b0, uint32_t b1) {
    asm volatile("mma.sync.aligned.m16n8k16.row.col.f32.bf16.bf16.f32 "
                 "{%0,%1,%2,%3},{%4,%5,%6,%7},{%8,%9},{%0,%1,%2,%3};"
                 : "+f"(d[0]), "+f"(d[1]), "+f"(d[2]), "+f"(d[3])
                 : "r"(a[0]), "r"(a[1]), "r"(a[2]), "r"(a[3]), "r"(b0), "r"(b1));
}
__device__ __forceinline__ void cpasync16(uint32_t s, const void* g) {
    asm volatile("cp.async.cg.shared.global [%0], [%1], 16;" :: "r"(s), "l"(g));
}
__device__ __forceinline__ void cp_commit() { asm volatile("cp.async.commit_group;"); }
template <int n> __device__ __forceinline__ void cp_wait() {
    asm volatile("cp.async.wait_group %0;" :: "n"(n));
}

// ================= split-bf16 tensor-core GEMM =================
// C[M,N] = A3[M,K''] * B3t[N,K'']^T (+epilogue), bf16 in / fp32 accum.
// Tile 128x256x64, 512 threads (16 warps 4x4), warp tile 32x64, 3-stage cp.async.
constexpr int EP_BIAS = 0;
constexpr int EP_KEY  = 1;
constexpr int EP_GELU = 2;
constexpr int EP_OUT  = 3;

#define STG 49152                    // 16KB A + 32KB B per stage
#define GEMM_SMEM (1024 + 3 * STG)   // align slack + 3 stages = 148480

template <int MODE>
__global__ void __launch_bounds__(512, 1)
gemm_mma(const __nv_bfloat16* __restrict__ A, const __nv_bfloat16* __restrict__ Bt,
         const float* __restrict__ bias, float* __restrict__ C, float* __restrict__ C2,
         const float* __restrict__ addsrc, int N, int K)
{
    extern __shared__ __align__(16) char smem_[];
    const uint32_t sbase = (s2u(smem_) + 1023u) & ~1023u;
    const int tid = threadIdx.x;
    const int lane = tid & 31, warp = tid >> 5;
    const int wm = warp >> 2, wn = warp & 3;
    const int brow = blockIdx.y, bcol = blockIdx.x;

    const __nv_bfloat16* Ag = A  + (size_t)brow * 128 * K;
    const __nv_bfloat16* Bg = Bt + (size_t)bcol * 256 * K;

    // loader: 3072 16B-chunks per stage (A:1024, B:2048), 6 per thread
    uint32_t so[6];
    const __nv_bfloat16* gp[6];
#pragma unroll
    for (int j = 0; j < 6; j++) {
        int id = tid + j * 512;
        int q; const __nv_bfloat16* base; uint32_t off;
        if (id < 1024) { q = id;        base = Ag; off = 0; }
        else           { q = id - 1024; base = Bg; off = 16384; }
        int r = q >> 3, c = q & 7;
        gp[j] = base + (size_t)r * K + c * 8;
        so[j] = off + r * 128 + ((uint32_t)(c ^ (r & 7)) << 4);
    }

    // ldmatrix per-lane precompute
    const int mat = lane >> 3, mr = lane & 7;
    const int chi = mat >> 1;
    uint32_t aBase[2]; int aXor[2];
#pragma unroll
    for (int mi = 0; mi < 2; mi++) {
        int row = wm * 32 + mi * 16 + mr + (mat & 1) * 8;
        aBase[mi] = row * 128;
        aXor[mi] = row & 7;
    }
    uint32_t bBase[4]; int bXor[4];
#pragma unroll
    for (int g = 0; g < 4; g++) {
        int row = wn * 64 + g * 16 + mr + (mat & 1) * 8;
        bBase[g] = 16384 + row * 128;
        bXor[g] = row & 7;
    }

    float acc[2][8][4];
#pragma unroll
    for (int i = 0; i < 2; i++)
#pragma unroll
        for (int j = 0; j < 8; j++)
#pragma unroll
            for (int q = 0; q < 4; q++) acc[i][j][q] = 0.f;

    const int nk = K >> 6;
    // prologue: stages 0 and 1
#pragma unroll
    for (int j = 0; j < 6; j++) cpasync16(sbase + so[j], gp[j]);
    cp_commit();
#pragma unroll
    for (int j = 0; j < 6; j++) { gp[j] += 64; cpasync16(sbase + STG + so[j], gp[j]); }
    cp_commit();

    for (int it = 0; it < nk; it++) {
        if (it < nk - 1) cp_wait<1>(); else cp_wait<0>();
        __syncthreads();
        if (it + 2 < nk) {
            const uint32_t dst = sbase + (uint32_t)((it + 2) % 3) * STG;
#pragma unroll
            for (int j = 0; j < 6; j++) { gp[j] += 64; cpasync16(dst + so[j], gp[j]); }
            cp_commit();
        }
        const uint32_t ps = sbase + (uint32_t)(it % 3) * STG;
#pragma unroll
        for (int kk = 0; kk < 4; kk++) {
            const int cb = kk * 2 + chi;
            uint32_t a0[4], a1[4];
            ldsm4(a0[0], a0[1], a0[2], a0[3], ps + aBase[0] + ((cb ^ aXor[0]) << 4));
            ldsm4(a1[0], a1[1], a1[2], a1[3], ps + aBase[1] + ((cb ^ aXor[1]) << 4));
#pragma unroll
            for (int g = 0; g < 4; g++) {
                uint32_t b0, b1, b2, b3;
                ldsm4(b0, b1, b2, b3, ps + bBase[g] + ((cb ^ bXor[g]) << 4));
                mma16816(acc[0][2 * g],     a0, b0, b2);
                mma16816(acc[0][2 * g + 1], a0, b1, b3);
                mma16816(acc[1][2 * g],     a1, b0, b2);
                mma16816(acc[1][2 * g + 1], a1, b1, b3);
            }
        }
    }

    // -------- epilogue --------
    const int r0 = brow * 128 + wm * 32 + (lane >> 2);
    const int c0 = bcol * 256 + wn * 64 + (lane & 3) * 2;
#pragma unroll
    for (int mi = 0; mi < 2; mi++) {
#pragma unroll
        for (int nj = 0; nj < 8; nj++) {
            const int col = c0 + nj * 8;
            const float bv0 = bias[col], bv1 = bias[col + 1];
#pragma unroll
            for (int h = 0; h < 2; h++) {
                const int row = r0 + mi * 16 + h * 8;
                const size_t base = (size_t)row * N + col;
                float v0 = acc[mi][nj][2 * h]     + bv0;
                float v1 = acc[mi][nj][2 * h + 1] + bv1;
                if (MODE == EP_GELU) {
                    v0 = 0.5f * v0 * (1.f + erff(v0 * 0.70710678118654752f));
                    v1 = 0.5f * v1 * (1.f + erff(v1 * 0.70710678118654752f));
                }
                if (MODE == EP_OUT) { v0 += addsrc[base]; v1 += addsrc[base + 1]; }
                if (MODE == EP_KEY) {
                    float s0, cc0, s1, cc1;
                    sincosf(tanhf(v0) * 3.14159265358979323846f, &s0, &cc0);
                    sincosf(tanhf(v1) * 3.14159265358979323846f, &s1, &cc1);
                    *reinterpret_cast<float2*>(C  + base) = make_float2(cc0, cc1);
                    *reinterpret_cast<float2*>(C2 + base) = make_float2(s0, s1);
                } else {
                    *reinterpret_cast<float2*>(C + base) = make_float2(v0, v1);
                }
            }
        }
    }
}

// ---------------- conversion kernels ----------------
// A-side: fp32 [M,K] -> bf16 [M,3K] triples (hi, lo, hi)
__global__ void k_cvtA(const float* __restrict__ in, __nv_bfloat16* __restrict__ out, int K)
{
    int t = blockIdx.x * 256 + threadIdx.x;        // one float4
    int q = K >> 2;
    int m = t / q, k4 = t % q;
    float4 v = reinterpret_cast<const float4*>(in)[(size_t)m * q + k4];
    float vv[4] = {v.x, v.y, v.z, v.w};
    __align__(8) __nv_bfloat16 o[12];
#pragma unroll
    for (int j = 0; j < 4; j++) {
        __nv_bfloat16 h = __float2bfloat16(vv[j]);
        __nv_bfloat16 l = __float2bfloat16(vv[j] - __bfloat162float(h));
        o[3 * j] = h; o[3 * j + 1] = l; o[3 * j + 2] = h;
    }
    uint2* dst = reinterpret_cast<uint2*>(out + (size_t)m * 3 * K + 12 * k4);
    const uint2* src = reinterpret_cast<const uint2*>(o);
    dst[0] = src[0]; dst[1] = src[1]; dst[2] = src[2];
}

// B-side: W[K,N] fp32 -> out[N][3K] bf16 triples (hi, hi, lo), via 32x33 smem transpose
__global__ void k_cvtB(const float* __restrict__ W, __nv_bfloat16* __restrict__ out, int K, int N)
{
    __shared__ float ts[32][33];
    const int k0 = blockIdx.y * 32, n0 = blockIdx.x * 32;
    const int tx = threadIdx.x, ty = threadIdx.y;   // (32,8)
#pragma unroll
    for (int i = 0; i < 4; i++)
        ts[ty + i * 8][tx] = W[(size_t)(k0 + ty + i * 8) * N + n0 + tx];
    __syncthreads();
#pragma unroll
    for (int i = 0; i < 4; i++) {
        int n = ty + i * 8;
        float w = ts[tx][n];
        __nv_bfloat16 h = __float2bfloat16(w);
        __nv_bfloat16 l = __float2bfloat16(w - __bfloat162float(h));
        size_t ob = (size_t)(n0 + n) * 3 * K + 3 * (size_t)(k0 + tx);
        out[ob] = h; out[ob + 1] = h; out[ob + 2] = l;
    }
}

// build [x3 | shift1(x3)] concat in triple space (16B chunks)
__global__ void k_xcat3(const __nv_bfloat16* __restrict__ x3, __nv_bfloat16* __restrict__ xc)
{
    int t = blockIdx.x * 256 + threadIdx.x;   // 768 uint4 per output row
    int row = t / 768, c = t % 768;
    uint4 v;
    if (c < 384) {
        v = reinterpret_cast<const uint4*>(x3)[(size_t)row * 384 + c];
    } else {
        int l = row & (LL - 1);
        if (l == 0) v = make_uint4(0, 0, 0, 0);
        else v = reinterpret_cast<const uint4*>(x3)[(size_t)(row - 1) * 384 + (c - 384)];
    }
    reinterpret_cast<uint4*>(xc)[t] = v;
}

// ---------------- value_gates: warp-per-row sigmoid(gh @ Wg2 + bg2) ----------------
__global__ void k_vg(const float* __restrict__ Wg2, const float* __restrict__ bg2)
{
    const int warp = threadIdx.x >> 5, lane = threadIdx.x & 31;
    const int row = blockIdx.x * 8 + warp;
    const float4* g = reinterpret_cast<const float4*>(g_gh + (size_t)row * DD);
    const float4* w = reinterpret_cast<const float4*>(Wg2);
    float s = 0.f;
#pragma unroll
    for (int i = 0; i < 8; i++) {
        float4 a = g[lane + i * 32], b = w[lane + i * 32];
        s += a.x * b.x + a.y * b.y + a.z * b.z + a.w * b.w;
    }
#pragma unroll
    for (int o = 16; o > 0; o >>= 1) s += __shfl_xor_sync(0xFFFFFFFFu, s, o);
    if (lane == 0) g_vg[row] = 1.f / (1.f + expf(-(s + bg2[0])));
}

// ---------------- blend weights: warp-per-row softmax(bh @ Wb2 + bb2) ----------------
__global__ void k_bw(const float* __restrict__ Wb2, const float* __restrict__ bb2)
{
    const int warp = threadIdx.x >> 5, lane = threadIdx.x & 31;
    const int row = blockIdx.x * 8 + warp;
    const float4* hv = reinterpret_cast<const float4*>(g_bh + (size_t)row * (DD / 2));
    const float4* wv = reinterpret_cast<const float4*>(Wb2);
    float s0 = 0.f, s1 = 0.f;
#pragma unroll
    for (int i = 0; i < 4; i++) {
        int idx = lane + i * 32;
        float4 a = hv[idx];
        float4 w0 = wv[2 * idx], w1 = wv[2 * idx + 1];
        s0 += a.x * w0.x + a.y * w0.z + a.z * w1.x + a.w * w1.z;
        s1 += a.x * w0.y + a.y * w0.w + a.z * w1.y + a.w * w1.w;
    }
#pragma unroll
    for (int o = 16; o > 0; o >>= 1) {
        s0 += __shfl_xor_sync(0xFFFFFFFFu, s0, o);
        s1 += __shfl_xor_sync(0xFFFFFFFFu, s1, o);
    }
    if (lane == 0) {
        float a0 = s0 + bb2[0], a1 = s1 + bb2[1];
        float m = fmaxf(a0, a1);
        float e0 = expf(a0 - m), e1 = expf(a1 - m);
        float inv = 1.f / (e0 + e1);
        g_bw[2 * row]     = e0 * inv;
        g_bw[2 * row + 1] = e1 * inv;
    }
}

// ---------------- per-batch gate scan ----------------
__global__ void k_gatescan()
{
    int b = blockIdx.x;
    __shared__ float sh[1024];
    float carry = 0.f;
    for (int t0 = 0; t0 < LL; t0 += 1024) {
        int l = t0 + threadIdx.x;
        sh[threadIdx.x] = g_vg[b * LL + l];
        __syncthreads();
        for (int off = 1; off < 1024; off <<= 1) {
            float tv = (threadIdx.x >= off) ? sh[threadIdx.x - off] : 0.f;
            __syncthreads();
            sh[threadIdx.x] += tv;
            __syncthreads();
        }
        float inc = sh[threadIdx.x] + carry;
        float tot = sh[1023];
        g_gcs[b * LL + l] = sqrtf(fmaxf(inc, 1.f));
        carry += tot;
        __syncthreads();
    }
}

// ---------------- scan pass A ----------------
__global__ void k_scanA(const float* __restrict__ pp)
{
    int d = blockIdx.x * 256 + threadIdx.x;
    int c = blockIdx.y, b = blockIdx.z;
    float spc = 0.f, sps = 0.f, skc = 0.f, sks = 0.f;
    int l0 = c * TCHUNK;
    for (int t = 0; t < TCHUNK; t++) {
        int l = l0 + t;
        int rowi = b * LL + l;
        size_t idx = (size_t)rowi * DD + d;
        float pvv = g_pv[idx];
        float sn, cs;
        sincosf(pp[(size_t)l * DD + d], &sn, &cs);
        spc = fmaf(cs, pvv, spc);
        sps = fmaf(sn, pvv, sps);
        float kvg = g_kv[idx] * g_vg[rowi];
        float kcp = (l == 0) ? 0.f : g_kc[idx - DD];
        float ksp = (l == 0) ? 0.f : g_ks[idx - DD];
        skc = fmaf(kcp, kvg, skc);
        sks = fmaf(ksp, kvg, sks);
        g_mpc[idx] = spc; g_mps[idx] = sps;
        g_mkc[idx] = skc; g_mks[idx] = sks;
    }
    size_t tix = (size_t)(b * NCHUNK + c) * DD + d;
    g_tot[tix]            = spc;
    g_tot[TOTN + tix]     = sps;
    g_tot[2 * TOTN + tix] = skc;
    g_tot[3 * TOTN + tix] = sks;
}

// ---------------- scan pass C ----------------
__global__ void k_scanC(const float* __restrict__ pp)
{
    int d = blockIdx.x * 256 + threadIdx.x;
    int c = blockIdx.y, b = blockIdx.z;
    float opc = 0.f, ops = 0.f, okc = 0.f, oks = 0.f;
    for (int cc = 0; cc < c; cc++) {
        size_t tix = (size_t)(b * NCHUNK + cc) * DD + d;
        opc += g_tot[tix];
        ops += g_tot[TOTN + tix];
        okc += g_tot[2 * TOTN + tix];
        oks += g_tot[3 * TOTN + tix];
    }
    const float invSqrtD = 0.03125f;
    int l0 = c * TCHUNK;
    for (int t = 0; t < TCHUNK; t++) {
        int l = l0 + t;
        int rowi = b * LL + l;
        size_t idx = (size_t)rowi * DD + d;
        float sn, cs;
        sincosf(pp[(size_t)l * DD + d], &sn, &cs);
        float pos_ret = (cs * (g_mpc[idx] + opc) + sn * (g_mps[idx] + ops)) * invSqrtD;
        float kv_ret  = (g_kc[idx] * (g_mkc[idx] + okc) + g_ks[idx] * (g_mks[idx] + oks))
                        / g_gcs[rowi] * invSqrtD;
        g_blend[idx] = g_bw[2 * rowi] * pos_ret + g_bw[2 * rowi + 1] * kv_ret;
    }
}

// ---------------- LayerNorm fused with triple-split output ----------------
__global__ void k_ln(const float* __restrict__ lng, const float* __restrict__ lnb,
                     __nv_bfloat16* __restrict__ out3)
{
    int row = blockIdx.x, tid = threadIdx.x;
    float v[4], s = 0.f, sq = 0.f;
#pragma unroll
    for (int i = 0; i < 4; i++) {
        v[i] = g_blend[(size_t)row * DD + tid + i * 256];
        s += v[i]; sq += v[i] * v[i];
    }
    __shared__ float shs[256], shq[256];
    shs[tid] = s; shq[tid] = sq; __syncthreads();
    for (int o = 128; o > 0; o >>= 1) {
        if (tid < o) { shs[tid] += shs[tid + o]; shq[tid] += shq[tid + o]; }
        __syncthreads();
    }
    __shared__ float smu, srstd;
    if (tid == 0) {
        float mu  = shs[0] * (1.f / DD);
        float var = shq[0] * (1.f / DD) - mu * mu;
        smu = mu;
        srstd = rsqrtf(var + 1e-5f);
    }
    __syncthreads();
#pragma unroll
    for (int i = 0; i < 4; i++) {
        int dd = tid + i * 256;
        float t = (v[i] - smu) * srstd * lng[dd] + lnb[dd];
        __nv_bfloat16 h = __float2bfloat16(t);
        __nv_bfloat16 l = __float2bfloat16(t - __bfloat162float(h));
        size_t ob = (size_t)row * 3 * DD + 3 * (size_t)dd;
        out3[ob] = h; out3[ob + 1] = l; out3[ob + 2] = h;
    }
}

// ---------------- launch ----------------
extern "C" void kernel_launch(void* const* d_in, const int* in_sizes, int n_in,
                              void* d_out, int out_size)
{
    const float* x   = (const float*)d_in[0];
    const float* pp  = (const float*)d_in[1];
    const float* Wpv = (const float*)d_in[2];
    const float* bpv = (const float*)d_in[3];
    const float* Wk  = (const float*)d_in[4];
    const float* bk  = (const float*)d_in[5];
    const float* Wkv = (const float*)d_in[6];
    const float* bkv = (const float*)d_in[7];
    const float* Wg1 = (const float*)d_in[8];
    const float* bg1 = (const float*)d_in[9];
    const float* Wg2 = (const float*)d_in[10];
    const float* bg2 = (const float*)d_in[11];
    const float* Wb1 = (const float*)d_in[12];
    const float* bb1 = (const float*)d_in[13];
    const float* Wb2 = (const float*)d_in[14];
    const float* bb2 = (const float*)d_in[15];
    const float* lng = (const float*)d_in[16];
    const float* lnb = (const float*)d_in[17];
    const float* Wo  = (const float*)d_in[18];
    const float* bo  = (const float*)d_in[19];
    float* out = (float*)d_out;

    float *pv, *kc, *ks, *kv, *gh, *bh;
    cudaGetSymbolAddress((void**)&pv, g_pv);
    cudaGetSymbolAddress((void**)&kc, g_kc);
    cudaGetSymbolAddress((void**)&ks, g_ks);
    cudaGetSymbolAddress((void**)&kv, g_kv);
    cudaGetSymbolAddress((void**)&gh, g_gh);
    cudaGetSymbolAddress((void**)&bh, g_bh);

    __nv_bfloat16 *x3, *xc3, *ln3, *Wpv3, *Wk3, *Wkv3, *Wg13, *Wb13, *Wo3;
    cudaGetSymbolAddress((void**)&x3,   g_x3);
    cudaGetSymbolAddress((void**)&xc3,  g_xc3);
    cudaGetSymbolAddress((void**)&ln3,  g_ln3);
    cudaGetSymbolAddress((void**)&Wpv3, g_Wpv3);
    cudaGetSymbolAddress((void**)&Wk3,  g_Wk3);
    cudaGetSymbolAddress((void**)&Wkv3, g_Wkv3);
    cudaGetSymbolAddress((void**)&Wg13, g_Wg13);
    cudaGetSymbolAddress((void**)&Wb13, g_Wb13);
    cudaGetSymbolAddress((void**)&Wo3,  g_Wo3);

    cudaFuncSetAttribute(gemm_mma<EP_BIAS>, cudaFuncAttributeMaxDynamicSharedMemorySize, GEMM_SMEM);
    cudaFuncSetAttribute(gemm_mma<EP_KEY >, cudaFuncAttributeMaxDynamicSharedMemorySize, GEMM_SMEM);
    cudaFuncSetAttribute(gemm_mma<EP_GELU>, cudaFuncAttributeMaxDynamicSharedMemorySize, GEMM_SMEM);
    cudaFuncSetAttribute(gemm_mma<EP_OUT >, cudaFuncAttributeMaxDynamicSharedMemorySize, GEMM_SMEM);

    // conversions: activations + weights -> split-bf16 triples
    k_cvtA<<<(MM * DD / 4) / 256, 256>>>(x, x3, DD);
    k_xcat3<<<(MM * 768) / 256, 256>>>(x3, xc3);
    k_cvtB<<<dim3(DD / 32, DD / 32),       dim3(32, 8)>>>(Wpv, Wpv3, DD,     DD);
    k_cvtB<<<dim3(DD / 32, DD / 32),       dim3(32, 8)>>>(Wk,  Wk3,  DD,     DD);
    k_cvtB<<<dim3(DD / 32, DD / 32),       dim3(32, 8)>>>(Wkv, Wkv3, DD,     DD);
    k_cvtB<<<dim3(DD / 32, 2 * DD / 32),   dim3(32, 8)>>>(Wg1, Wg13, 2 * DD, DD);
    k_cvtB<<<dim3((DD / 2) / 32, DD / 32), dim3(32, 8)>>>(Wb1, Wb13, DD,     DD / 2);
    k_cvtB<<<dim3(DD / 32, DD / 32),       dim3(32, 8)>>>(Wo,  Wo3,  DD,     DD);

    dim3 g1024(DD / 256, MM / 128);        // (4, 128)
    dim3 g512((DD / 2) / 256, MM / 128);   // (2, 128)

    // tensor-core GEMMs with fused epilogues (virtual K'' = 3K)
    gemm_mma<EP_BIAS><<<g1024, 512, GEMM_SMEM>>>(x3,  Wpv3, bpv, pv, nullptr, nullptr, DD,     3 * DD);
    gemm_mma<EP_KEY ><<<g1024, 512, GEMM_SMEM>>>(x3,  Wk3,  bk,  kc, ks,      nullptr, DD,     3 * DD);
    gemm_mma<EP_BIAS><<<g1024, 512, GEMM_SMEM>>>(x3,  Wkv3, bkv, kv, nullptr, nullptr, DD,     3 * DD);
    gemm_mma<EP_GELU><<<g1024, 512, GEMM_SMEM>>>(xc3, Wg13, bg1, gh, nullptr, nullptr, DD,     6 * DD);
    gemm_mma<EP_GELU><<<g512,  512, GEMM_SMEM>>>(x3,  Wb13, bb1, bh, nullptr, nullptr, DD / 2, 3 * DD);

    // gates / blend / scans
    k_vg<<<MM / 8, 256>>>(Wg2, bg2);
    k_bw<<<MM / 8, 256>>>(Wb2, bb2);
    k_gatescan<<<BBATCH, 1024>>>();
    dim3 gscan(DD / 256, NCHUNK, BBATCH);
    k_scanA<<<gscan, 256>>>(pp);
    k_scanC<<<gscan, 256>>>(pp);

    // LayerNorm (fused triple-split) -> output GEMM (+residual)
    k_ln<<<MM, 256>>>(lng, lnb, ln3);
    gemm_mma<EP_OUT><<<g1024, 512, GEMM_SMEM>>>(ln3, Wo3, bo, out, nullptr, x, DD, 3 * DD);
}

// round 7
// speedup vs baseline: 1.0573x; 1.0573x over previous
#include <cuda_runtime.h>
#include <cuda_bf16.h>
#include <math.h>
#include <stdint.h>

// ---------------- problem constants ----------------
#define BBATCH 4
#define LL 4096
#define DD 1024
#define MM (BBATCH * LL)          // 16384 rows
#define NCHUNK 64
#define TCHUNK (LL / NCHUNK)      // 64
#define TOTN (BBATCH * NCHUNK * DD)

// ---------------- fp32 scratch ----------------
__device__ float g_pv[(size_t)MM * DD];
__device__ float g_kc[(size_t)MM * DD];
__device__ float g_ks[(size_t)MM * DD];
__device__ float g_kv[(size_t)MM * DD];
__device__ float g_gh[(size_t)MM * DD];
__device__ float g_bh[(size_t)MM * (DD / 2)];
__device__ float g_vg[MM];
__device__ float g_gcs[MM];
__device__ float g_bw[MM * 2];
__device__ float g_tot[4 * TOTN];
__device__ float g_blend[(size_t)MM * DD];
__device__ float g_pc[(size_t)LL * DD];   // cos(pos_phases)
__device__ float g_ps[(size_t)LL * DD];   // sin(pos_phases)

// ---------------- bf16 split-triple scratch ----------------
// A-side triple per k: (hi, lo, hi). B-side [N][3K] triple: (hi, hi, lo).
__device__ __nv_bfloat16 g_x3 [(size_t)MM * 3 * DD];
__device__ __nv_bfloat16 g_ln3[(size_t)MM * 3 * DD];
__device__ __nv_bfloat16 g_Wqkv3[(size_t)3 * 3 * DD * DD];   // [3 slices][1024 rows][3K]
__device__ __nv_bfloat16 g_Wg13[(size_t)6 * DD * DD];
__device__ __nv_bfloat16 g_Wb13[(size_t)3 * DD * (DD / 2)];
__device__ __nv_bfloat16 g_Wo3 [(size_t)3 * DD * DD];

// ================= PTX helpers (family-safe) =================
__device__ __forceinline__ uint32_t s2u(const void* p) {
    return (uint32_t)__cvta_generic_to_shared(p);
}
__device__ __forceinline__ void ldsm4(uint32_t& r0, uint32_t& r1, uint32_t& r2, uint32_t& r3, uint32_t a) {
    asm volatile("ldmatrix.sync.aligned.m8n8.x4.shared.b16 {%0,%1,%2,%3}, [%4];"
                 : "=r"(r0), "=r"(r1), "=r"(r2), "=r"(r3) : "r"(a));
}
__device__ __forceinline__ void mma16816(float* d, const uint32_t* a, uint32_t b0, uint32_t b1) {
    asm volatile("mma.sync.aligned.m16n8k16.row.col.f32.bf16.bf16.f32 "
                 "{%0,%1,%2,%3},{%4,%5,%6,%7},{%8,%9},{%0,%1,%2,%3};"
                 : "+f"(d[0]), "+f"(d[1]), "+f"(d[2]), "+f"(d[3])
                 : "r"(a[0]), "r"(a[1]), "r"(a[2]), "r"(a[3]), "r"(b0), "r"(b1));
}
__device__ __forceinline__ void cpasync16(uint32_t s, const void* g) {
    asm volatile("cp.async.cg.shared.global [%0], [%1], 16;" :: "r"(s), "l"(g));
}
__device__ __forceinline__ void sts_zero16(uint32_t a) {
    asm volatile("st.shared.v4.b32 [%0], {%1,%1,%1,%1};" :: "r"(a), "r"(0) : "memory");
}
__device__ __forceinline__ void cp_commit() { asm volatile("cp.async.commit_group;"); }
template <int n> __device__ __forceinline__ void cp_wait() {
    asm volatile("cp.async.wait_group %0;" :: "n"(n));
}

// ================= GEMM core shared pieces =================
// Tile 128x256x64, 512 threads (16 warps 4x4), warp tile 32x64, 3-stage cp.async.
constexpr int EP_GELU = 2;
constexpr int EP_OUT  = 3;

#define STG 49152
#define GEMM_SMEM (1024 + 3 * STG)

struct MmaCtx {
    uint32_t aBase[2]; int aXor[2];
    uint32_t bBase[4]; int bXor[4];
    int chi;
};
__device__ __forceinline__ void mma_ctx_init(MmaCtx& cx, int lane, int wm, int wn) {
    const int mat = lane >> 3, mr = lane & 7;
    cx.chi = mat >> 1;
#pragma unroll
    for (int mi = 0; mi < 2; mi++) {
        int row = wm * 32 + mi * 16 + mr + (mat & 1) * 8;
        cx.aBase[mi] = row * 128; cx.aXor[mi] = row & 7;
    }
#pragma unroll
    for (int g = 0; g < 4; g++) {
        int row = wn * 64 + g * 16 + mr + (mat & 1) * 8;
        cx.bBase[g] = 16384 + row * 128; cx.bXor[g] = row & 7;
    }
}
__device__ __forceinline__ void mma_tile(const MmaCtx& cx, uint32_t ps, float acc[2][8][4]) {
#pragma unroll
    for (int kk = 0; kk < 4; kk++) {
        const int cb = kk * 2 + cx.chi;
        uint32_t a0[4], a1[4];
        ldsm4(a0[0], a0[1], a0[2], a0[3], ps + cx.aBase[0] + ((cb ^ cx.aXor[0]) << 4));
        ldsm4(a1[0], a1[1], a1[2], a1[3], ps + cx.aBase[1] + ((cb ^ cx.aXor[1]) << 4));
#pragma unroll
        for (int g = 0; g < 4; g++) {
            uint32_t b0, b1, b2, b3;
            ldsm4(b0, b1, b2, b3, ps + cx.bBase[g] + ((cb ^ cx.bXor[g]) << 4));
            mma16816(acc[0][2 * g],     a0, b0, b2);
            mma16816(acc[0][2 * g + 1], a0, b1, b3);
            mma16816(acc[1][2 * g],     a1, b0, b2);
            mma16816(acc[1][2 * g + 1], a1, b1, b3);
        }
    }
}

// ================= generic GEMM (gelu / out epilogues) =================
template <int MODE>
__global__ void __launch_bounds__(512, 1)
gemm_mma(const __nv_bfloat16* __restrict__ A, const __nv_bfloat16* __restrict__ Bt,
         const float* __restrict__ bias, float* __restrict__ C,
         const float* __restrict__ addsrc, int N, int K)
{
    extern __shared__ __align__(16) char smem_[];
    const uint32_t sbase = (s2u(smem_) + 1023u) & ~1023u;
    const int tid = threadIdx.x, lane = tid & 31, warp = tid >> 5;
    const int wm = warp >> 2, wn = warp & 3;
    const int brow = blockIdx.y, bcol = blockIdx.x;

    const __nv_bfloat16* Ag = A  + (size_t)brow * 128 * K;
    const __nv_bfloat16* Bg = Bt + (size_t)bcol * 256 * K;

    uint32_t so[6];
    const __nv_bfloat16* gp[6];
#pragma unroll
    for (int j = 0; j < 6; j++) {
        int id = tid + j * 512;
        int q; const __nv_bfloat16* base; uint32_t off;
        if (id < 1024) { q = id;        base = Ag; off = 0; }
        else           { q = id - 1024; base = Bg; off = 16384; }
        int r = q >> 3, c = q & 7;
        gp[j] = base + (size_t)r * K + c * 8;
        so[j] = off + r * 128 + ((uint32_t)(c ^ (r & 7)) << 4);
    }
    MmaCtx cx; mma_ctx_init(cx, lane, wm, wn);

    float acc[2][8][4];
#pragma unroll
    for (int i = 0; i < 2; i++)
#pragma unroll
        for (int j = 0; j < 8; j++)
#pragma unroll
            for (int q = 0; q < 4; q++) acc[i][j][q] = 0.f;

    const int nk = K >> 6;
#pragma unroll
    for (int j = 0; j < 6; j++) cpasync16(sbase + so[j], gp[j]);
    cp_commit();
#pragma unroll
    for (int j = 0; j < 6; j++) { gp[j] += 64; cpasync16(sbase + STG + so[j], gp[j]); }
    cp_commit();

    for (int it = 0; it < nk; it++) {
        if (it < nk - 1) cp_wait<1>(); else cp_wait<0>();
        __syncthreads();
        if (it + 2 < nk) {
            const uint32_t dst = sbase + (uint32_t)((it + 2) % 3) * STG;
#pragma unroll
            for (int j = 0; j < 6; j++) { gp[j] += 64; cpasync16(dst + so[j], gp[j]); }
            cp_commit();
        }
        mma_tile(cx, sbase + (uint32_t)(it % 3) * STG, acc);
    }

    const int r0 = brow * 128 + wm * 32 + (lane >> 2);
    const int c0 = bcol * 256 + wn * 64 + (lane & 3) * 2;
#pragma unroll
    for (int mi = 0; mi < 2; mi++) {
#pragma unroll
        for (int nj = 0; nj < 8; nj++) {
            const int col = c0 + nj * 8;
            const float bv0 = bias[col], bv1 = bias[col + 1];
#pragma unroll
            for (int h = 0; h < 2; h++) {
                const int row = r0 + mi * 16 + h * 8;
                const size_t base = (size_t)row * N + col;
                float v0 = acc[mi][nj][2 * h]     + bv0;
                float v1 = acc[mi][nj][2 * h + 1] + bv1;
                if (MODE == EP_GELU) {
                    v0 = 0.5f * v0 * (1.f + erff(v0 * 0.70710678118654752f));
                    v1 = 0.5f * v1 * (1.f + erff(v1 * 0.70710678118654752f));
                }
                if (MODE == EP_OUT) { v0 += addsrc[base]; v1 += addsrc[base + 1]; }
                *reinterpret_cast<float2*>(C + base) = make_float2(v0, v1);
            }
        }
    }
}

// ================= merged QKV GEMM (N=3072, dispatch epilogue) =================
__global__ void __launch_bounds__(512, 1)
gemm_qkv(const __nv_bfloat16* __restrict__ A, const __nv_bfloat16* __restrict__ Bt,
         const float* __restrict__ bpv, const float* __restrict__ bk, const float* __restrict__ bkv,
         float* __restrict__ pv, float* __restrict__ kc, float* __restrict__ ks,
         float* __restrict__ kv)
{
    extern __shared__ __align__(16) char smem_[];
    const uint32_t sbase = (s2u(smem_) + 1023u) & ~1023u;
    const int tid = threadIdx.x, lane = tid & 31, warp = tid >> 5;
    const int wm = warp >> 2, wn = warp & 3;
    const int brow = blockIdx.y, bcol = blockIdx.x;
    const int K = 3 * DD;

    const __nv_bfloat16* Ag = A  + (size_t)brow * 128 * K;
    const __nv_bfloat16* Bg = Bt + (size_t)bcol * 256 * K;

    uint32_t so[6];
    const __nv_bfloat16* gp[6];
#pragma unroll
    for (int j = 0; j < 6; j++) {
        int id = tid + j * 512;
        int q; const __nv_bfloat16* base; uint32_t off;
        if (id < 1024) { q = id;        base = Ag; off = 0; }
        else           { q = id - 1024; base = Bg; off = 16384; }
        int r = q >> 3, c = q & 7;
        gp[j] = base + (size_t)r * K + c * 8;
        so[j] = off + r * 128 + ((uint32_t)(c ^ (r & 7)) << 4);
    }
    MmaCtx cx; mma_ctx_init(cx, lane, wm, wn);

    float acc[2][8][4];
#pragma unroll
    for (int i = 0; i < 2; i++)
#pragma unroll
        for (int j = 0; j < 8; j++)
#pragma unroll
            for (int q = 0; q < 4; q++) acc[i][j][q] = 0.f;

    const int nk = K >> 6;    // 48
#pragma unroll
    for (int j = 0; j < 6; j++) cpasync16(sbase + so[j], gp[j]);
    cp_commit();
#pragma unroll
    for (int j = 0; j < 6; j++) { gp[j] += 64; cpasync16(sbase + STG + so[j], gp[j]); }
    cp_commit();

    for (int it = 0; it < nk; it++) {
        if (it < nk - 1) cp_wait<1>(); else cp_wait<0>();
        __syncthreads();
        if (it + 2 < nk) {
            const uint32_t dst = sbase + (uint32_t)((it + 2) % 3) * STG;
#pragma unroll
            for (int j = 0; j < 6; j++) { gp[j] += 64; cpasync16(dst + so[j], gp[j]); }
            cp_commit();
        }
        mma_tile(cx, sbase + (uint32_t)(it % 3) * STG, acc);
    }

    const int sect = bcol >> 2;                 // 0: pv, 1: key, 2: kv
    const float* bias = (sect == 0) ? bpv : (sect == 1) ? bk : bkv;
    float* Cm = (sect == 0) ? pv : kv;
    const int r0 = brow * 128 + wm * 32 + (lane >> 2);
    const int c0 = (bcol & 3) * 256 + wn * 64 + (lane & 3) * 2;
#pragma unroll
    for (int mi = 0; mi < 2; mi++) {
#pragma unroll
        for (int nj = 0; nj < 8; nj++) {
            const int col = c0 + nj * 8;
            const float bv0 = bias[col], bv1 = bias[col + 1];
#pragma unroll
            for (int h = 0; h < 2; h++) {
                const int row = r0 + mi * 16 + h * 8;
                const size_t base = (size_t)row * DD + col;
                float v0 = acc[mi][nj][2 * h]     + bv0;
                float v1 = acc[mi][nj][2 * h + 1] + bv1;
                if (sect == 1) {
                    float s0, cc0, s1, cc1;
                    sincosf(tanhf(v0) * 3.14159265358979323846f, &s0, &cc0);
                    sincosf(tanhf(v1) * 3.14159265358979323846f, &s1, &cc1);
                    *reinterpret_cast<float2*>(kc + base) = make_float2(cc0, cc1);
                    *reinterpret_cast<float2*>(ks + base) = make_float2(s0, s1);
                } else {
                    *reinterpret_cast<float2*>(Cm + base) = make_float2(v0, v1);
                }
            }
        }
    }
}

// ================= gate GEMM: A = [x3 | shift1(x3)] virtual concat =================
__global__ void __launch_bounds__(512, 1)
gemm_gate(const __nv_bfloat16* __restrict__ X3, const __nv_bfloat16* __restrict__ Bt,
          const float* __restrict__ bias, float* __restrict__ C)
{
    extern __shared__ __align__(16) char smem_[];
    const uint32_t sbase = (s2u(smem_) + 1023u) & ~1023u;
    const int tid = threadIdx.x, lane = tid & 31, warp = tid >> 5;
    const int wm = warp >> 2, wn = warp & 3;
    const int brow = blockIdx.y, bcol = blockIdx.x;
    const int K = 6 * DD;         // virtual K'' = 6144
    const int KH = 3 * DD;        // half = 3072

    // A chunks (j=0,1): dual-base
    uint32_t soA[2];
    const __nv_bfloat16 *aCur[2], *aPrev[2];
    bool validA[2];
#pragma unroll
    for (int j = 0; j < 2; j++) {
        int q = tid + j * 512;          // 0..1023
        int r = q >> 3, c = q & 7;
        int R = brow * 128 + r;
        aCur[j]  = X3 + (size_t)R * KH + c * 8;
        aPrev[j] = X3 + ((size_t)R - 1) * KH + c * 8;
        validA[j] = (R & (LL - 1)) != 0;
        soA[j] = r * 128 + ((uint32_t)(c ^ (r & 7)) << 4);
    }
    // B chunks (j=0..3)
    uint32_t soB[4];
    const __nv_bfloat16* bgp[4];
#pragma unroll
    for (int j = 0; j < 4; j++) {
        int q = tid + j * 512;          // 0..2047
        int r = q >> 3, c = q & 7;
        bgp[j] = Bt + (size_t)(bcol * 256 + r) * K + c * 8;
        soB[j] = 16384 + r * 128 + ((uint32_t)(c ^ (r & 7)) << 4);
    }
    MmaCtx cx; mma_ctx_init(cx, lane, wm, wn);

    float acc[2][8][4];
#pragma unroll
    for (int i = 0; i < 2; i++)
#pragma unroll
        for (int j = 0; j < 8; j++)
#pragma unroll
            for (int q = 0; q < 4; q++) acc[i][j][q] = 0.f;

    const int nk = K >> 6;    // 96
#define GATE_LOAD(ITP, DST)                                                        \
    do {                                                                           \
        int itp_ = (ITP);                                                          \
        if (itp_ < 48) {                                                           \
            cpasync16((DST) + soA[0], aCur[0] + itp_ * 64);                        \
            cpasync16((DST) + soA[1], aCur[1] + itp_ * 64);                        \
        } else {                                                                   \
            if (validA[0]) cpasync16((DST) + soA[0], aPrev[0] + (itp_ - 48) * 64); \
            else sts_zero16((DST) + soA[0]);                                       \
            if (validA[1]) cpasync16((DST) + soA[1], aPrev[1] + (itp_ - 48) * 64); \
            else sts_zero16((DST) + soA[1]);                                       \
        }                                                                          \
        cpasync16((DST) + soB[0], bgp[0] + itp_ * 64);                             \
        cpasync16((DST) + soB[1], bgp[1] + itp_ * 64);                             \
        cpasync16((DST) + soB[2], bgp[2] + itp_ * 64);                             \
        cpasync16((DST) + soB[3], bgp[3] + itp_ * 64);                             \
        cp_commit();                                                               \
    } while (0)

    GATE_LOAD(0, sbase);
    GATE_LOAD(1, sbase + STG);

    for (int it = 0; it < nk; it++) {
        if (it < nk - 1) cp_wait<1>(); else cp_wait<0>();
        __syncthreads();
        if (it + 2 < nk) {
            const uint32_t dst = sbase + (uint32_t)((it + 2) % 3) * STG;
            GATE_LOAD(it + 2, dst);
        }
        mma_tile(cx, sbase + (uint32_t)(it % 3) * STG, acc);
    }
#undef GATE_LOAD

    const int r0 = brow * 128 + wm * 32 + (lane >> 2);
    const int c0 = bcol * 256 + wn * 64 + (lane & 3) * 2;
#pragma unroll
    for (int mi = 0; mi < 2; mi++) {
#pragma unroll
        for (int nj = 0; nj < 8; nj++) {
            const int col = c0 + nj * 8;
            const float bv0 = bias[col], bv1 = bias[col + 1];
#pragma unroll
            for (int h = 0; h < 2; h++) {
                const int row = r0 + mi * 16 + h * 8;
                const size_t base = (size_t)row * DD + col;
                float v0 = acc[mi][nj][2 * h]     + bv0;
                float v1 = acc[mi][nj][2 * h + 1] + bv1;
                v0 = 0.5f * v0 * (1.f + erff(v0 * 0.70710678118654752f));
                v1 = 0.5f * v1 * (1.f + erff(v1 * 0.70710678118654752f));
                *reinterpret_cast<float2*>(C + base) = make_float2(v0, v1);
            }
        }
    }
}

// ---------------- conversion kernels ----------------
__global__ void k_cvtA(const float* __restrict__ in, __nv_bfloat16* __restrict__ out, int K)
{
    int t = blockIdx.x * 256 + threadIdx.x;
    int q = K >> 2;
    int m = t / q, k4 = t % q;
    float4 v = reinterpret_cast<const float4*>(in)[(size_t)m * q + k4];
    float vv[4] = {v.x, v.y, v.z, v.w};
    __align__(8) __nv_bfloat16 o[12];
#pragma unroll
    for (int j = 0; j < 4; j++) {
        __nv_bfloat16 h = __float2bfloat16(vv[j]);
        __nv_bfloat16 l = __float2bfloat16(vv[j] - __bfloat162float(h));
        o[3 * j] = h; o[3 * j + 1] = l; o[3 * j + 2] = h;
    }
    uint2* dst = reinterpret_cast<uint2*>(out + (size_t)m * 3 * K + 12 * k4);
    const uint2* src = reinterpret_cast<const uint2*>(o);
    dst[0] = src[0]; dst[1] = src[1]; dst[2] = src[2];
}

__global__ void k_cvtB(const float* __restrict__ W, __nv_bfloat16* __restrict__ out, int K, int N)
{
    __shared__ float ts[32][33];
    const int k0 = blockIdx.y * 32, n0 = blockIdx.x * 32;
    const int tx = threadIdx.x, ty = threadIdx.y;
#pragma unroll
    for (int i = 0; i < 4; i++)
        ts[ty + i * 8][tx] = W[(size_t)(k0 + ty + i * 8) * N + n0 + tx];
    __syncthreads();
#pragma unroll
    for (int i = 0; i < 4; i++) {
        int n = ty + i * 8;
        float w = ts[tx][n];
        __nv_bfloat16 h = __float2bfloat16(w);
        __nv_bfloat16 l = __float2bfloat16(w - __bfloat162float(h));
        size_t ob = (size_t)(n0 + n) * 3 * K + 3 * (size_t)(k0 + tx);
        out[ob] = h; out[ob + 1] = h; out[ob + 2] = l;
    }
}

// 3 square weights -> one packed [3][1024][3K] buffer, one launch
__global__ void k_cvtB3(const float* __restrict__ W0, const float* __restrict__ W1,
                        const float* __restrict__ W2, __nv_bfloat16* __restrict__ out)
{
    __shared__ float ts[32][33];
    const float* W = (blockIdx.z == 0) ? W0 : (blockIdx.z == 1) ? W1 : W2;
    __nv_bfloat16* o = out + (size_t)blockIdx.z * DD * 3 * DD;
    const int k0 = blockIdx.y * 32, n0 = blockIdx.x * 32;
    const int tx = threadIdx.x, ty = threadIdx.y;
#pragma unroll
    for (int i = 0; i < 4; i++)
        ts[ty + i * 8][tx] = W[(size_t)(k0 + ty + i * 8) * DD + n0 + tx];
    __syncthreads();
#pragma unroll
    for (int i = 0; i < 4; i++) {
        int n = ty + i * 8;
        float w = ts[tx][n];
        __nv_bfloat16 h = __float2bfloat16(w);
        __nv_bfloat16 l = __float2bfloat16(w - __bfloat162float(h));
        size_t ob = (size_t)(n0 + n) * 3 * DD + 3 * (size_t)(k0 + tx);
        o[ob] = h; o[ob + 1] = h; o[ob + 2] = l;
    }
}

// precompute cos/sin of pos_phases
__global__ void k_sincos(const float* __restrict__ pp)
{
    size_t t = (size_t)blockIdx.x * 256 + threadIdx.x;
    float sn, cs;
    sincosf(pp[t], &sn, &cs);
    g_pc[t] = cs; g_ps[t] = sn;
}

// ---------------- value_gates ----------------
__global__ void k_vg(const float* __restrict__ Wg2, const float* __restrict__ bg2)
{
    const int warp = threadIdx.x >> 5, lane = threadIdx.x & 31;
    const int row = blockIdx.x * 8 + warp;
    const float4* g = reinterpret_cast<const float4*>(g_gh + (size_t)row * DD);
    const float4* w = reinterpret_cast<const float4*>(Wg2);
    float s = 0.f;
#pragma unroll
    for (int i = 0; i < 8; i++) {
        float4 a = g[lane + i * 32], b = w[lane + i * 32];
        s += a.x * b.x + a.y * b.y + a.z * b.z + a.w * b.w;
    }
#pragma unroll
    for (int o = 16; o > 0; o >>= 1) s += __shfl_xor_sync(0xFFFFFFFFu, s, o);
    if (lane == 0) g_vg[row] = 1.f / (1.f + expf(-(s + bg2[0])));
}

// ---------------- blend weights ----------------
__global__ void k_bw(const float* __restrict__ Wb2, const float* __restrict__ bb2)
{
    const int warp = threadIdx.x >> 5, lane = threadIdx.x & 31;
    const int row = blockIdx.x * 8 + warp;
    const float4* hv = reinterpret_cast<const float4*>(g_bh + (size_t)row * (DD / 2));
    const float4* wv = reinterpret_cast<const float4*>(Wb2);
    float s0 = 0.f, s1 = 0.f;
#pragma unroll
    for (int i = 0; i < 4; i++) {
        int idx = lane + i * 32;
        float4 a = hv[idx];
        float4 w0 = wv[2 * idx], w1 = wv[2 * idx + 1];
        s0 += a.x * w0.x + a.y * w0.z + a.z * w1.x + a.w * w1.z;
        s1 += a.x * w0.y + a.y * w0.w + a.z * w1.y + a.w * w1.w;
    }
#pragma unroll
    for (int o = 16; o > 0; o >>= 1) {
        s0 += __shfl_xor_sync(0xFFFFFFFFu, s0, o);
        s1 += __shfl_xor_sync(0xFFFFFFFFu, s1, o);
    }
    if (lane == 0) {
        float a0 = s0 + bb2[0], a1 = s1 + bb2[1];
        float m = fmaxf(a0, a1);
        float e0 = expf(a0 - m), e1 = expf(a1 - m);
        float inv = 1.f / (e0 + e1);
        g_bw[2 * row]     = e0 * inv;
        g_bw[2 * row + 1] = e1 * inv;
    }
}

// ---------------- per-batch gate scan ----------------
__global__ void k_gatescan()
{
    int b = blockIdx.x;
    __shared__ float sh[1024];
    float carry = 0.f;
    for (int t0 = 0; t0 < LL; t0 += 1024) {
        int l = t0 + threadIdx.x;
        sh[threadIdx.x] = g_vg[b * LL + l];
        __syncthreads();
        for (int off = 1; off < 1024; off <<= 1) {
            float tv = (threadIdx.x >= off) ? sh[threadIdx.x - off] : 0.f;
            __syncthreads();
            sh[threadIdx.x] += tv;
            __syncthreads();
        }
        float inc = sh[threadIdx.x] + carry;
        float tot = sh[1023];
        g_gcs[b * LL + l] = sqrtf(fmaxf(inc, 1.f));
        carry += tot;
        __syncthreads();
    }
}

// ---------------- scan pass T: per-chunk totals only ----------------
__global__ void k_scanT()
{
    int d = blockIdx.x * 256 + threadIdx.x;
    int c = blockIdx.y, b = blockIdx.z;
    float spc = 0.f, sps = 0.f, skc = 0.f, sks = 0.f;
    int l0 = c * TCHUNK;
    for (int t = 0; t < TCHUNK; t++) {
        int l = l0 + t;
        int rowi = b * LL + l;
        size_t idx = (size_t)rowi * DD + d;
        size_t pidx = (size_t)l * DD + d;
        float pvv = g_pv[idx];
        spc = fmaf(g_pc[pidx], pvv, spc);
        sps = fmaf(g_ps[pidx], pvv, sps);
        float kvg = g_kv[idx] * g_vg[rowi];
        float kcp = (l == 0) ? 0.f : g_kc[idx - DD];
        float ksp = (l == 0) ? 0.f : g_ks[idx - DD];
        skc = fmaf(kcp, kvg, skc);
        sks = fmaf(ksp, kvg, sks);
    }
    size_t tix = (size_t)(b * NCHUNK + c) * DD + d;
    g_tot[tix]            = spc;
    g_tot[TOTN + tix]     = sps;
    g_tot[2 * TOTN + tix] = skc;
    g_tot[3 * TOTN + tix] = sks;
}

// ---------------- scan pass C: offsets + local cumsum recompute + blend ----------------
__global__ void k_scanC()
{
    int d = blockIdx.x * 256 + threadIdx.x;
    int c = blockIdx.y, b = blockIdx.z;
    float opc = 0.f, ops = 0.f, okc = 0.f, oks = 0.f;
    for (int cc = 0; cc < c; cc++) {
        size_t tix = (size_t)(b * NCHUNK + cc) * DD + d;
        opc += g_tot[tix];
        ops += g_tot[TOTN + tix];
        okc += g_tot[2 * TOTN + tix];
        oks += g_tot[3 * TOTN + tix];
    }
    const float invSqrtD = 0.03125f;
    int l0 = c * TCHUNK;
    float spc = 0.f, sps = 0.f, skc = 0.f, sks = 0.f;
    for (int t = 0; t < TCHUNK; t++) {
        int l = l0 + t;
        int rowi = b * LL + l;
        size_t idx = (size_t)rowi * DD + d;
        size_t pidx = (size_t)l * DD + d;
        float pvv = g_pv[idx];
        float cs = g_pc[pidx], sn = g_ps[pidx];
        spc = fmaf(cs, pvv, spc);
        sps = fmaf(sn, pvv, sps);
        float kvg = g_kv[idx] * g_vg[rowi];
        float kcc = g_kc[idx], kss = g_ks[idx];
        float kcp = (l == 0) ? 0.f : g_kc[idx - DD];
        float ksp = (l == 0) ? 0.f : g_ks[idx - DD];
        skc = fmaf(kcp, kvg, skc);
        sks = fmaf(ksp, kvg, sks);
        float pos_ret = (cs * (spc + opc) + sn * (sps + ops)) * invSqrtD;
        float kv_ret  = (kcc * (skc + okc) + kss * (sks + oks)) / g_gcs[rowi] * invSqrtD;
        g_blend[idx] = g_bw[2 * rowi] * pos_ret + g_bw[2 * rowi + 1] * kv_ret;
    }
}

// ---------------- LayerNorm fused with triple-split output ----------------
__global__ void k_ln(const float* __restrict__ lng, const float* __restrict__ lnb,
                     __nv_bfloat16* __restrict__ out3)
{
    int row = blockIdx.x, tid = threadIdx.x;
    float v[4], s = 0.f, sq = 0.f;
#pragma unroll
    for (int i = 0; i < 4; i++) {
        v[i] = g_blend[(size_t)row * DD + tid + i * 256];
        s += v[i]; sq += v[i] * v[i];
    }
    __shared__ float shs[256], shq[256];
    shs[tid] = s; shq[tid] = sq; __syncthreads();
    for (int o = 128; o > 0; o >>= 1) {
        if (tid < o) { shs[tid] += shs[tid + o]; shq[tid] += shq[tid + o]; }
        __syncthreads();
    }
    __shared__ float smu, srstd;
    if (tid == 0) {
        float mu  = shs[0] * (1.f / DD);
        float var = shq[0] * (1.f / DD) - mu * mu;
        smu = mu;
        srstd = rsqrtf(var + 1e-5f);
    }
    __syncthreads();
#pragma unroll
    for (int i = 0; i < 4; i++) {
        int dd = tid + i * 256;
        float t = (v[i] - smu) * srstd * lng[dd] + lnb[dd];
        __nv_bfloat16 h = __float2bfloat16(t);
        __nv_bfloat16 l = __float2bfloat16(t - __bfloat162float(h));
        size_t ob = (size_t)row * 3 * DD + 3 * (size_t)dd;
        out3[ob] = h; out3[ob + 1] = l; out3[ob + 2] = h;
    }
}

// ---------------- launch ----------------
extern "C" void kernel_launch(void* const* d_in, const int* in_sizes, int n_in,
                              void* d_out, int out_size)
{
    const float* x   = (const float*)d_in[0];
    const float* pp  = (const float*)d_in[1];
    const float* Wpv = (const float*)d_in[2];
    const float* bpv = (const float*)d_in[3];
    const float* Wk  = (const float*)d_in[4];
    const float* bk  = (const float*)d_in[5];
    const float* Wkv = (const float*)d_in[6];
    const float* bkv = (const float*)d_in[7];
    const float* Wg1 = (const float*)d_in[8];
    const float* bg1 = (const float*)d_in[9];
    const float* Wg2 = (const float*)d_in[10];
    const float* bg2 = (const float*)d_in[11];
    const float* Wb1 = (const float*)d_in[12];
    const float* bb1 = (const float*)d_in[13];
    const float* Wb2 = (const float*)d_in[14];
    const float* bb2 = (const float*)d_in[15];
    const float* lng = (const float*)d_in[16];
    const float* lnb = (const float*)d_in[17];
    const float* Wo  = (const float*)d_in[18];
    const float* bo  = (const float*)d_in[19];
    float* out = (float*)d_out;

    float *pv, *kc, *ks, *kv, *gh, *bh;
    cudaGetSymbolAddress((void**)&pv, g_pv);
    cudaGetSymbolAddress((void**)&kc, g_kc);
    cudaGetSymbolAddress((void**)&ks, g_ks);
    cudaGetSymbolAddress((void**)&kv, g_kv);
    cudaGetSymbolAddress((void**)&gh, g_gh);
    cudaGetSymbolAddress((void**)&bh, g_bh);

    __nv_bfloat16 *x3, *ln3, *Wqkv3, *Wg13, *Wb13, *Wo3;
    cudaGetSymbolAddress((void**)&x3,    g_x3);
    cudaGetSymbolAddress((void**)&ln3,   g_ln3);
    cudaGetSymbolAddress((void**)&Wqkv3, g_Wqkv3);
    cudaGetSymbolAddress((void**)&Wg13,  g_Wg13);
    cudaGetSymbolAddress((void**)&Wb13,  g_Wb13);
    cudaGetSymbolAddress((void**)&Wo3,   g_Wo3);

    cudaFuncSetAttribute(gemm_mma<EP_GELU>, cudaFuncAttributeMaxDynamicSharedMemorySize, GEMM_SMEM);
    cudaFuncSetAttribute(gemm_mma<EP_OUT >, cudaFuncAttributeMaxDynamicSharedMemorySize, GEMM_SMEM);
    cudaFuncSetAttribute(gemm_qkv,  cudaFuncAttributeMaxDynamicSharedMemorySize, GEMM_SMEM);
    cudaFuncSetAttribute(gemm_gate, cudaFuncAttributeMaxDynamicSharedMemorySize, GEMM_SMEM);

    // 0: activations -> triples
    k_cvtA<<<(MM * DD / 4) / 256, 256>>>(x, x3, DD);
    // 1: qkv weights (one launch)
    k_cvtB3<<<dim3(DD / 32, DD / 32, 3), dim3(32, 8)>>>(Wpv, Wk, Wkv, Wqkv3);
    // 2: pos phase cos/sin
    k_sincos<<<(LL * DD) / 256, 256>>>(pp);
    // 3: merged QKV GEMM (N=3072)
    gemm_qkv<<<dim3(12, MM / 128), 512, GEMM_SMEM>>>(x3, Wqkv3, bpv, bk, bkv, pv, kc, ks, kv);
    // 4: gate weights
    k_cvtB<<<dim3(DD / 32, 2 * DD / 32), dim3(32, 8)>>>(Wg1, Wg13, 2 * DD, DD);
    // 5: gate GEMM (virtual concat A, K''=6144)
    gemm_gate<<<dim3(4, MM / 128), 512, GEMM_SMEM>>>(x3, Wg13, bg1, gh);
    // 6: blend weights path
    k_cvtB<<<dim3((DD / 2) / 32, DD / 32), dim3(32, 8)>>>(Wb1, Wb13, DD, DD / 2);
    // 7
    gemm_mma<EP_GELU><<<dim3(2, MM / 128), 512, GEMM_SMEM>>>(x3, Wb13, bb1, bh, nullptr, DD / 2, 3 * DD);
    // 8-10: gates / blend softmax / gate cumsum
    k_vg<<<MM / 8, 256>>>(Wg2, bg2);
    k_bw<<<MM / 8, 256>>>(Wb2, bb2);
    k_gatescan<<<BBATCH, 1024>>>();
    // 11-12: scans
    dim3 gscan(DD / 256, NCHUNK, BBATCH);
    k_scanT<<<gscan, 256>>>();
    k_scanC<<<gscan, 256>>>();
    // 13: LayerNorm (fused triple-split)
    k_ln<<<MM, 256>>>(lng, lnb, ln3);
    // 14-15: output path
    k_cvtB<<<dim3(DD / 32, DD / 32), dim3(32, 8)>>>(Wo, Wo3, DD, DD);
    gemm_mma<EP_OUT><<<dim3(4, MM / 128), 512, GEMM_SMEM>>>(ln3, Wo3, bo, out, x, DD, 3 * DD);
}

// round 8
// speedup vs baseline: 1.3783x; 1.3036x over previous
#include <cuda_runtime.h>
#include <cuda_bf16.h>
#include <cuda_fp16.h>
#include <math.h>
#include <stdint.h>

// ---------------- problem constants ----------------
#define BBATCH 4
#define LL 4096
#define DD 1024
#define MM (BBATCH * LL)          // 16384 rows
#define NCHUNK 64
#define TCHUNK (LL / NCHUNK)      // 64
#define TOTN (BBATCH * NCHUNK * DD)

// ---------------- fp32 scratch ----------------
__device__ float g_pv[(size_t)MM * DD];
__device__ float g_kc[(size_t)MM * DD];
__device__ float g_ks[(size_t)MM * DD];
__device__ float g_kv[(size_t)MM * DD];
__device__ float g_gh[(size_t)MM * DD];
__device__ float g_bh[(size_t)MM * (DD / 2)];
__device__ float g_vg[MM];
__device__ float g_gcs[MM];
__device__ float g_bw[MM * 2];
__device__ float g_tot[4 * TOTN];
__device__ float g_blend[(size_t)MM * DD];
__device__ float g_pc[(size_t)LL * DD];   // cos(pos_phases)
__device__ float g_ps[(size_t)LL * DD];   // sin(pos_phases)

// ---------------- split-precision operand scratch ----------------
// bf16 triples (key path): A per k (hi,lo,hi); B [N][3K] per k (hi,hi,lo)
__device__ __nv_bfloat16 g_x3 [(size_t)MM * 3 * DD];
__device__ __nv_bfloat16 g_Wk3[(size_t)DD * 3 * DD];
// fp16 pairs (all other GEMMs): A per k (hi,lo); B [N][2K] per k (hi,hi)
__device__ __half g_x2   [(size_t)MM * 2 * DD];
__device__ __half g_ln2  [(size_t)MM * 2 * DD];
__device__ __half g_Wpvkv2[(size_t)2 * DD * 2 * DD];   // rows 0-1023: Wpv^T, 1024-2047: Wkv^T
__device__ __half g_Wg12 [(size_t)DD * 4 * DD];        // [1024][4096]
__device__ __half g_Wb12 [(size_t)(DD / 2) * 2 * DD];  // [512][2048]
__device__ __half g_Wo2  [(size_t)DD * 2 * DD];

// ================= PTX helpers (family-safe) =================
__device__ __forceinline__ uint32_t s2u(const void* p) {
    return (uint32_t)__cvta_generic_to_shared(p);
}
__device__ __forceinline__ void ldsm4(uint32_t& r0, uint32_t& r1, uint32_t& r2, uint32_t& r3, uint32_t a) {
    asm volatile("ldmatrix.sync.aligned.m8n8.x4.shared.b16 {%0,%1,%2,%3}, [%4];"
                 : "=r"(r0), "=r"(r1), "=r"(r2), "=r"(r3) : "r"(a));
}
template <bool F16>
__device__ __forceinline__ void mma16816(float* d, const uint32_t* a, uint32_t b0, uint32_t b1);
template <>
__device__ __forceinline__ void mma16816<false>(float* d, const uint32_t* a, uint32_t b0, uint32_t b1) {
    asm volatile("mma.sync.aligned.m16n8k16.row.col.f32.bf16.bf16.f32 "
                 "{%0,%1,%2,%3},{%4,%5,%6,%7},{%8,%9},{%0,%1,%2,%3};"
                 : "+f"(d[0]), "+f"(d[1]), "+f"(d[2]), "+f"(d[3])
                 : "r"(a[0]), "r"(a[1]), "r"(a[2]), "r"(a[3]), "r"(b0), "r"(b1));
}
template <>
__device__ __forceinline__ void mma16816<true>(float* d, const uint32_t* a, uint32_t b0, uint32_t b1) {
    asm volatile("mma.sync.aligned.m16n8k16.row.col.f32.f16.f16.f32 "
                 "{%0,%1,%2,%3},{%4,%5,%6,%7},{%8,%9},{%0,%1,%2,%3};"
                 : "+f"(d[0]), "+f"(d[1]), "+f"(d[2]), "+f"(d[3])
                 : "r"(a[0]), "r"(a[1]), "r"(a[2]), "r"(a[3]), "r"(b0), "r"(b1));
}
__device__ __forceinline__ void cpasync16(uint32_t s, const void* g) {
    asm volatile("cp.async.cg.shared.global [%0], [%1], 16;" :: "r"(s), "l"(g));
}
__device__ __forceinline__ void sts_zero16(uint32_t a) {
    asm volatile("st.shared.v4.b32 [%0], {%1,%1,%1,%1};" :: "r"(a), "r"(0) : "memory");
}
__device__ __forceinline__ void cp_commit() { asm volatile("cp.async.commit_group;"); }
template <int n> __device__ __forceinline__ void cp_wait() {
    asm volatile("cp.async.wait_group %0;" :: "n"(n));
}

// ================= GEMM core shared pieces =================
// Tile 128x256x64(virtual k-elems), 512 threads (16 warps 4x4), warp tile 32x64, 3-stage.
constexpr int EP_KEY  = 1;
constexpr int EP_GELU = 2;
constexpr int EP_OUT  = 3;
constexpr int EP_PVKV = 4;

#define STG 49152
#define GEMM_SMEM (1024 + 3 * STG)

struct MmaCtx {
    uint32_t aBase[2]; int aXor[2];
    uint32_t bBase[4]; int bXor[4];
    int chi;
};
__device__ __forceinline__ void mma_ctx_init(MmaCtx& cx, int lane, int wm, int wn) {
    const int mat = lane >> 3, mr = lane & 7;
    cx.chi = mat >> 1;
#pragma unroll
    for (int mi = 0; mi < 2; mi++) {
        int row = wm * 32 + mi * 16 + mr + (mat & 1) * 8;
        cx.aBase[mi] = row * 128; cx.aXor[mi] = row & 7;
    }
#pragma unroll
    for (int g = 0; g < 4; g++) {
        int row = wn * 64 + g * 16 + mr + (mat & 1) * 8;
        cx.bBase[g] = 16384 + row * 128; cx.bXor[g] = row & 7;
    }
}
template <bool F16>
__device__ __forceinline__ void mma_tile(const MmaCtx& cx, uint32_t ps, float acc[2][8][4]) {
#pragma unroll
    for (int kk = 0; kk < 4; kk++) {
        const int cb = kk * 2 + cx.chi;
        uint32_t a0[4], a1[4];
        ldsm4(a0[0], a0[1], a0[2], a0[3], ps + cx.aBase[0] + ((cb ^ cx.aXor[0]) << 4));
        ldsm4(a1[0], a1[1], a1[2], a1[3], ps + cx.aBase[1] + ((cb ^ cx.aXor[1]) << 4));
#pragma unroll
        for (int g = 0; g < 4; g++) {
            uint32_t b0, b1, b2, b3;
            ldsm4(b0, b1, b2, b3, ps + cx.bBase[g] + ((cb ^ cx.bXor[g]) << 4));
            mma16816<F16>(acc[0][2 * g],     a0, b0, b2);
            mma16816<F16>(acc[0][2 * g + 1], a0, b1, b3);
            mma16816<F16>(acc[1][2 * g],     a1, b0, b2);
            mma16816<F16>(acc[1][2 * g + 1], a1, b1, b3);
        }
    }
}

// ================= generic GEMM =================
// A: [M][K] 2-byte elems (virtual K). Bt: [N][K]. MODE selects epilogue.
template <int MODE, bool F16>
__global__ void __launch_bounds__(512, 1)
gemm_mma(const uint16_t* __restrict__ A, const uint16_t* __restrict__ Bt,
         const float* __restrict__ bias, const float* __restrict__ bias2,
         float* __restrict__ C, float* __restrict__ C2,
         const float* __restrict__ addsrc, int N, int K)
{
    extern __shared__ __align__(16) char smem_[];
    const uint32_t sbase = (s2u(smem_) + 1023u) & ~1023u;
    const int tid = threadIdx.x, lane = tid & 31, warp = tid >> 5;
    const int wm = warp >> 2, wn = warp & 3;
    const int brow = blockIdx.y, bcol = blockIdx.x;

    const uint16_t* Ag = A  + (size_t)brow * 128 * K;
    const uint16_t* Bg = Bt + (size_t)bcol * 256 * K;

    uint32_t so[6];
    const uint16_t* gp[6];
#pragma unroll
    for (int j = 0; j < 6; j++) {
        int id = tid + j * 512;
        int q; const uint16_t* base; uint32_t off;
        if (id < 1024) { q = id;        base = Ag; off = 0; }
        else           { q = id - 1024; base = Bg; off = 16384; }
        int r = q >> 3, c = q & 7;
        gp[j] = base + (size_t)r * K + c * 8;
        so[j] = off + r * 128 + ((uint32_t)(c ^ (r & 7)) << 4);
    }
    MmaCtx cx; mma_ctx_init(cx, lane, wm, wn);

    float acc[2][8][4];
#pragma unroll
    for (int i = 0; i < 2; i++)
#pragma unroll
        for (int j = 0; j < 8; j++)
#pragma unroll
            for (int q = 0; q < 4; q++) acc[i][j][q] = 0.f;

    const int nk = K >> 6;
#pragma unroll
    for (int j = 0; j < 6; j++) cpasync16(sbase + so[j], gp[j]);
    cp_commit();
#pragma unroll
    for (int j = 0; j < 6; j++) { gp[j] += 64; cpasync16(sbase + STG + so[j], gp[j]); }
    cp_commit();

    for (int it = 0; it < nk; it++) {
        if (it < nk - 1) cp_wait<1>(); else cp_wait<0>();
        __syncthreads();
        if (it + 2 < nk) {
            const uint32_t dst = sbase + (uint32_t)((it + 2) % 3) * STG;
#pragma unroll
            for (int j = 0; j < 6; j++) { gp[j] += 64; cpasync16(dst + so[j], gp[j]); }
            cp_commit();
        }
        mma_tile<F16>(cx, sbase + (uint32_t)(it % 3) * STG, acc);
    }

    // -------- epilogue --------
    const int r0 = brow * 128 + wm * 32 + (lane >> 2);
    // PVKV: route halves to separate buffers (output stride DD)
    const int sect = (MODE == EP_PVKV) ? (bcol >> 2) : 0;
    const float* bp = (MODE == EP_PVKV && sect) ? bias2 : bias;
    float* Cp = (MODE == EP_PVKV && sect) ? C2 : C;
    const int ostride = (MODE == EP_PVKV) ? DD : N;
    const int c0 = ((MODE == EP_PVKV) ? ((bcol & 3) * 256) : (bcol * 256)) + wn * 64 + (lane & 3) * 2;
#pragma unroll
    for (int mi = 0; mi < 2; mi++) {
#pragma unroll
        for (int nj = 0; nj < 8; nj++) {
            const int col = c0 + nj * 8;
            const float bv0 = bp[col], bv1 = bp[col + 1];
#pragma unroll
            for (int h = 0; h < 2; h++) {
                const int row = r0 + mi * 16 + h * 8;
                const size_t base = (size_t)row * ostride + col;
                float v0 = acc[mi][nj][2 * h]     + bv0;
                float v1 = acc[mi][nj][2 * h + 1] + bv1;
                if (MODE == EP_GELU) {
                    v0 = 0.5f * v0 * (1.f + erff(v0 * 0.70710678118654752f));
                    v1 = 0.5f * v1 * (1.f + erff(v1 * 0.70710678118654752f));
                }
                if (MODE == EP_OUT) { v0 += addsrc[base]; v1 += addsrc[base + 1]; }
                if (MODE == EP_KEY) {
                    float s0, cc0, s1, cc1;
                    sincosf(tanhf(v0) * 3.14159265358979323846f, &s0, &cc0);
                    sincosf(tanhf(v1) * 3.14159265358979323846f, &s1, &cc1);
                    *reinterpret_cast<float2*>(C  + base) = make_float2(cc0, cc1);
                    *reinterpret_cast<float2*>(C2 + base) = make_float2(s0, s1);
                } else {
                    *reinterpret_cast<float2*>(Cp + base) = make_float2(v0, v1);
                }
            }
        }
    }
}

// ================= gate GEMM: A = [x2 | shift1(x2)] virtual concat (fp16 pairs) =================
__global__ void __launch_bounds__(512, 1)
gemm_gate(const uint16_t* __restrict__ X2, const uint16_t* __restrict__ Bt,
          const float* __restrict__ bias, float* __restrict__ C)
{
    extern __shared__ __align__(16) char smem_[];
    const uint32_t sbase = (s2u(smem_) + 1023u) & ~1023u;
    const int tid = threadIdx.x, lane = tid & 31, warp = tid >> 5;
    const int wm = warp >> 2, wn = warp & 3;
    const int brow = blockIdx.y, bcol = blockIdx.x;
    const int K = 4 * DD;         // virtual K'' = 4096
    const int KH = 2 * DD;        // half = 2048
    const int nkh = 32;           // K-chunks per half

    uint32_t soA[2];
    const uint16_t *aCur[2], *aPrev[2];
    bool validA[2];
#pragma unroll
    for (int j = 0; j < 2; j++) {
        int q = tid + j * 512;
        int r = q >> 3, c = q & 7;
        int R = brow * 128 + r;
        aCur[j]  = X2 + (size_t)R * KH + c * 8;
        aPrev[j] = X2 + ((size_t)R - 1) * KH + c * 8;
        validA[j] = (R & (LL - 1)) != 0;
        soA[j] = r * 128 + ((uint32_t)(c ^ (r & 7)) << 4);
    }
    uint32_t soB[4];
    const uint16_t* bgp[4];
#pragma unroll
    for (int j = 0; j < 4; j++) {
        int q = tid + j * 512;
        int r = q >> 3, c = q & 7;
        bgp[j] = Bt + (size_t)(bcol * 256 + r) * K + c * 8;
        soB[j] = 16384 + r * 128 + ((uint32_t)(c ^ (r & 7)) << 4);
    }
    MmaCtx cx; mma_ctx_init(cx, lane, wm, wn);

    float acc[2][8][4];
#pragma unroll
    for (int i = 0; i < 2; i++)
#pragma unroll
        for (int j = 0; j < 8; j++)
#pragma unroll
            for (int q = 0; q < 4; q++) acc[i][j][q] = 0.f;

    const int nk = K >> 6;   // 64
#define GATE_LOAD(ITP, DST)                                                           \
    do {                                                                              \
        int itp_ = (ITP);                                                             \
        if (itp_ < nkh) {                                                             \
            cpasync16((DST) + soA[0], aCur[0] + itp_ * 64);                           \
            cpasync16((DST) + soA[1], aCur[1] + itp_ * 64);                           \
        } else {                                                                      \
            if (validA[0]) cpasync16((DST) + soA[0], aPrev[0] + (itp_ - nkh) * 64);   \
            else sts_zero16((DST) + soA[0]);                                          \
            if (validA[1]) cpasync16((DST) + soA[1], aPrev[1] + (itp_ - nkh) * 64);   \
            else sts_zero16((DST) + soA[1]);                                          \
        }                                                                             \
        cpasync16((DST) + soB[0], bgp[0] + itp_ * 64);                                \
        cpasync16((DST) + soB[1], bgp[1] + itp_ * 64);                                \
        cpasync16((DST) + soB[2], bgp[2] + itp_ * 64);                                \
        cpasync16((DST) + soB[3], bgp[3] + itp_ * 64);                                \
        cp_commit();                                                                  \
    } while (0)

    GATE_LOAD(0, sbase);
    GATE_LOAD(1, sbase + STG);

    for (int it = 0; it < nk; it++) {
        if (it < nk - 1) cp_wait<1>(); else cp_wait<0>();
        __syncthreads();
        if (it + 2 < nk) {
            const uint32_t dst = sbase + (uint32_t)((it + 2) % 3) * STG;
            GATE_LOAD(it + 2, dst);
        }
        mma_tile<true>(cx, sbase + (uint32_t)(it % 3) * STG, acc);
    }
#undef GATE_LOAD

    const int r0 = brow * 128 + wm * 32 + (lane >> 2);
    const int c0 = bcol * 256 + wn * 64 + (lane & 3) * 2;
#pragma unroll
    for (int mi = 0; mi < 2; mi++) {
#pragma unroll
        for (int nj = 0; nj < 8; nj++) {
            const int col = c0 + nj * 8;
            const float bv0 = bias[col], bv1 = bias[col + 1];
#pragma unroll
            for (int h = 0; h < 2; h++) {
                const int row = r0 + mi * 16 + h * 8;
                const size_t base = (size_t)row * DD + col;
                float v0 = acc[mi][nj][2 * h]     + bv0;
                float v1 = acc[mi][nj][2 * h + 1] + bv1;
                v0 = 0.5f * v0 * (1.f + erff(v0 * 0.70710678118654752f));
                v1 = 0.5f * v1 * (1.f + erff(v1 * 0.70710678118654752f));
                *reinterpret_cast<float2*>(C + base) = make_float2(v0, v1);
            }
        }
    }
}

// ---------------- conversion kernels ----------------
// x -> bf16 triples (hi, lo, hi)
__global__ void k_cvtA3(const float* __restrict__ in, __nv_bfloat16* __restrict__ out)
{
    int t = blockIdx.x * 256 + threadIdx.x;
    int m = t >> 8, k4 = t & 255;
    float4 v = reinterpret_cast<const float4*>(in)[(size_t)m * 256 + k4];
    float vv[4] = {v.x, v.y, v.z, v.w};
    __align__(8) __nv_bfloat16 o[12];
#pragma unroll
    for (int j = 0; j < 4; j++) {
        __nv_bfloat16 h = __float2bfloat16(vv[j]);
        __nv_bfloat16 l = __float2bfloat16(vv[j] - __bfloat162float(h));
        o[3 * j] = h; o[3 * j + 1] = l; o[3 * j + 2] = h;
    }
    uint2* dst = reinterpret_cast<uint2*>(out + (size_t)m * 3 * DD + 12 * k4);
    const uint2* src = reinterpret_cast<const uint2*>(o);
    dst[0] = src[0]; dst[1] = src[1]; dst[2] = src[2];
}

// x -> fp16 pairs (hi, lo)
__global__ void k_cvtA2(const float* __restrict__ in, __half* __restrict__ out)
{
    int t = blockIdx.x * 256 + threadIdx.x;
    int m = t >> 8, k4 = t & 255;
    float4 v = reinterpret_cast<const float4*>(in)[(size_t)m * 256 + k4];
    float vv[4] = {v.x, v.y, v.z, v.w};
    __align__(16) __half o[8];
#pragma unroll
    for (int j = 0; j < 4; j++) {
        __half h = __float2half(vv[j]);
        __half l = __float2half(vv[j] - __half2float(h));
        o[2 * j] = h; o[2 * j + 1] = l;
    }
    reinterpret_cast<uint4*>(out + (size_t)m * 2 * DD + 8 * k4)[0] =
        *reinterpret_cast<const uint4*>(o);
}

// W[K,N] fp32 -> bf16 [N][3K] triples (hi, hi, lo)
__global__ void k_cvtB3(const float* __restrict__ W, __nv_bfloat16* __restrict__ out, int K, int N)
{
    __shared__ float ts[32][33];
    const int k0 = blockIdx.y * 32, n0 = blockIdx.x * 32;
    const int tx = threadIdx.x, ty = threadIdx.y;
#pragma unroll
    for (int i = 0; i < 4; i++)
        ts[ty + i * 8][tx] = W[(size_t)(k0 + ty + i * 8) * N + n0 + tx];
    __syncthreads();
#pragma unroll
    for (int i = 0; i < 4; i++) {
        int n = ty + i * 8;
        float w = ts[tx][n];
        __nv_bfloat16 h = __float2bfloat16(w);
        __nv_bfloat16 l = __float2bfloat16(w - __bfloat162float(h));
        size_t ob = (size_t)(n0 + n) * 3 * K + 3 * (size_t)(k0 + tx);
        out[ob] = h; out[ob + 1] = h; out[ob + 2] = l;
    }
}

// W[K,N] fp32 -> fp16 [N][2K] pairs (hi, hi)
__global__ void k_cvtB2(const float* __restrict__ W, __half* __restrict__ out, int K, int N)
{
    __shared__ float ts[32][33];
    const int k0 = blockIdx.y * 32, n0 = blockIdx.x * 32;
    const int tx = threadIdx.x, ty = threadIdx.y;
#pragma unroll
    for (int i = 0; i < 4; i++)
        ts[ty + i * 8][tx] = W[(size_t)(k0 + ty + i * 8) * N + n0 + tx];
    __syncthreads();
#pragma unroll
    for (int i = 0; i < 4; i++) {
        int n = ty + i * 8;
        __half h = __float2half(ts[tx][n]);
        size_t ob = (size_t)(n0 + n) * 2 * K + 2 * (size_t)(k0 + tx);
        out[ob] = h; out[ob + 1] = h;
    }
}

// precompute cos/sin of pos_phases
__global__ void k_sincos(const float* __restrict__ pp)
{
    size_t t = (size_t)blockIdx.x * 256 + threadIdx.x;
    float sn, cs;
    sincosf(pp[t], &sn, &cs);
    g_pc[t] = cs; g_ps[t] = sn;
}

// ---------------- value_gates ----------------
__global__ void k_vg(const float* __restrict__ Wg2, const float* __restrict__ bg2)
{
    const int warp = threadIdx.x >> 5, lane = threadIdx.x & 31;
    const int row = blockIdx.x * 8 + warp;
    const float4* g = reinterpret_cast<const float4*>(g_gh + (size_t)row * DD);
    const float4* w = reinterpret_cast<const float4*>(Wg2);
    float s = 0.f;
#pragma unroll
    for (int i = 0; i < 8; i++) {
        float4 a = g[lane + i * 32], b = w[lane + i * 32];
        s += a.x * b.x + a.y * b.y + a.z * b.z + a.w * b.w;
    }
#pragma unroll
    for (int o = 16; o > 0; o >>= 1) s += __shfl_xor_sync(0xFFFFFFFFu, s, o);
    if (lane == 0) g_vg[row] = 1.f / (1.f + expf(-(s + bg2[0])));
}

// ---------------- blend weights ----------------
__global__ void k_bw(const float* __restrict__ Wb2, const float* __restrict__ bb2)
{
    const int warp = threadIdx.x >> 5, lane = threadIdx.x & 31;
    const int row = blockIdx.x * 8 + warp;
    const float4* hv = reinterpret_cast<const float4*>(g_bh + (size_t)row * (DD / 2));
    const float4* wv = reinterpret_cast<const float4*>(Wb2);
    float s0 = 0.f, s1 = 0.f;
#pragma unroll
    for (int i = 0; i < 4; i++) {
        int idx = lane + i * 32;
        float4 a = hv[idx];
        float4 w0 = wv[2 * idx], w1 = wv[2 * idx + 1];
        s0 += a.x * w0.x + a.y * w0.z + a.z * w1.x + a.w * w1.z;
        s1 += a.x * w0.y + a.y * w0.w + a.z * w1.y + a.w * w1.w;
    }
#pragma unroll
    for (int o = 16; o > 0; o >>= 1) {
        s0 += __shfl_xor_sync(0xFFFFFFFFu, s0, o);
        s1 += __shfl_xor_sync(0xFFFFFFFFu, s1, o);
    }
    if (lane == 0) {
        float a0 = s0 + bb2[0], a1 = s1 + bb2[1];
        float m = fmaxf(a0, a1);
        float e0 = expf(a0 - m), e1 = expf(a1 - m);
        float inv = 1.f / (e0 + e1);
        g_bw[2 * row]     = e0 * inv;
        g_bw[2 * row + 1] = e1 * inv;
    }
}

// ---------------- per-batch gate scan ----------------
__global__ void k_gatescan()
{
    int b = blockIdx.x;
    __shared__ float sh[1024];
    float carry = 0.f;
    for (int t0 = 0; t0 < LL; t0 += 1024) {
        int l = t0 + threadIdx.x;
        sh[threadIdx.x] = g_vg[b * LL + l];
        __syncthreads();
        for (int off = 1; off < 1024; off <<= 1) {
            float tv = (threadIdx.x >= off) ? sh[threadIdx.x - off] : 0.f;
            __syncthreads();
            sh[threadIdx.x] += tv;
            __syncthreads();
        }
        float inc = sh[threadIdx.x] + carry;
        float tot = sh[1023];
        g_gcs[b * LL + l] = sqrtf(fmaxf(inc, 1.f));
        carry += tot;
        __syncthreads();
    }
}

// ---------------- scan pass T: per-chunk totals only ----------------
__global__ void k_scanT()
{
    int d = blockIdx.x * 256 + threadIdx.x;
    int c = blockIdx.y, b = blockIdx.z;
    float spc = 0.f, sps = 0.f, skc = 0.f, sks = 0.f;
    int l0 = c * TCHUNK;
    for (int t = 0; t < TCHUNK; t++) {
        int l = l0 + t;
        int rowi = b * LL + l;
        size_t idx = (size_t)rowi * DD + d;
        size_t pidx = (size_t)l * DD + d;
        float pvv = g_pv[idx];
        spc = fmaf(g_pc[pidx], pvv, spc);
        sps = fmaf(g_ps[pidx], pvv, sps);
        float kvg = g_kv[idx] * g_vg[rowi];
        float kcp = (l == 0) ? 0.f : g_kc[idx - DD];
        float ksp = (l == 0) ? 0.f : g_ks[idx - DD];
        skc = fmaf(kcp, kvg, skc);
        sks = fmaf(ksp, kvg, sks);
    }
    size_t tix = (size_t)(b * NCHUNK + c) * DD + d;
    g_tot[tix]            = spc;
    g_tot[TOTN + tix]     = sps;
    g_tot[2 * TOTN + tix] = skc;
    g_tot[3 * TOTN + tix] = sks;
}

// ---------------- scan pass C: offsets + local cumsum recompute + blend ----------------
__global__ void k_scanC()
{
    int d = blockIdx.x * 256 + threadIdx.x;
    int c = blockIdx.y, b = blockIdx.z;
    float opc = 0.f, ops = 0.f, okc = 0.f, oks = 0.f;
    for (int cc = 0; cc < c; cc++) {
        size_t tix = (size_t)(b * NCHUNK + cc) * DD + d;
        opc += g_tot[tix];
        ops += g_tot[TOTN + tix];
        okc += g_tot[2 * TOTN + tix];
        oks += g_tot[3 * TOTN + tix];
    }
    const float invSqrtD = 0.03125f;
    int l0 = c * TCHUNK;
    float spc = 0.f, sps = 0.f, skc = 0.f, sks = 0.f;
    for (int t = 0; t < TCHUNK; t++) {
        int l = l0 + t;
        int rowi = b * LL + l;
        size_t idx = (size_t)rowi * DD + d;
        size_t pidx = (size_t)l * DD + d;
        float pvv = g_pv[idx];
        float cs = g_pc[pidx], sn = g_ps[pidx];
        spc = fmaf(cs, pvv, spc);
        sps = fmaf(sn, pvv, sps);
        float kvg = g_kv[idx] * g_vg[rowi];
        float kcc = g_kc[idx], kss = g_ks[idx];
        float kcp = (l == 0) ? 0.f : g_kc[idx - DD];
        float ksp = (l == 0) ? 0.f : g_ks[idx - DD];
        skc = fmaf(kcp, kvg, skc);
        sks = fmaf(ksp, kvg, sks);
        float pos_ret = (cs * (spc + opc) + sn * (sps + ops)) * invSqrtD;
        float kv_ret  = (kcc * (skc + okc) + kss * (sks + oks)) / g_gcs[rowi] * invSqrtD;
        g_blend[idx] = g_bw[2 * rowi] * pos_ret + g_bw[2 * rowi + 1] * kv_ret;
    }
}

// ---------------- LayerNorm fused with fp16 pair-split output ----------------
__global__ void k_ln(const float* __restrict__ lng, const float* __restrict__ lnb,
                     __half* __restrict__ out2)
{
    int row = blockIdx.x, tid = threadIdx.x;
    float v[4], s = 0.f, sq = 0.f;
#pragma unroll
    for (int i = 0; i < 4; i++) {
        v[i] = g_blend[(size_t)row * DD + tid + i * 256];
        s += v[i]; sq += v[i] * v[i];
    }
    __shared__ float shs[256], shq[256];
    shs[tid] = s; shq[tid] = sq; __syncthreads();
    for (int o = 128; o > 0; o >>= 1) {
        if (tid < o) { shs[tid] += shs[tid + o]; shq[tid] += shq[tid + o]; }
        __syncthreads();
    }
    __shared__ float smu, srstd;
    if (tid == 0) {
        float mu  = shs[0] * (1.f / DD);
        float var = shq[0] * (1.f / DD) - mu * mu;
        smu = mu;
        srstd = rsqrtf(var + 1e-5f);
    }
    __syncthreads();
#pragma unroll
    for (int i = 0; i < 4; i++) {
        int dd = tid + i * 256;
        float t = (v[i] - smu) * srstd * lng[dd] + lnb[dd];
        __half h = __float2half(t);
        __half l = __float2half(t - __half2float(h));
        __half2 hl = __halves2half2(h, l);
        *reinterpret_cast<__half2*>(out2 + (size_t)row * 2 * DD + 2 * dd) = hl;
    }
}

// ---------------- launch ----------------
extern "C" void kernel_launch(void* const* d_in, const int* in_sizes, int n_in,
                              void* d_out, int out_size)
{
    const float* x   = (const float*)d_in[0];
    const float* pp  = (const float*)d_in[1];
    const float* Wpv = (const float*)d_in[2];
    const float* bpv = (const float*)d_in[3];
    const float* Wk  = (const float*)d_in[4];
    const float* bk  = (const float*)d_in[5];
    const float* Wkv = (const float*)d_in[6];
    const float* bkv = (const float*)d_in[7];
    const float* Wg1 = (const float*)d_in[8];
    const float* bg1 = (const float*)d_in[9];
    const float* Wg2 = (const float*)d_in[10];
    const float* bg2 = (const float*)d_in[11];
    const float* Wb1 = (const float*)d_in[12];
    const float* bb1 = (const float*)d_in[13];
    const float* Wb2 = (const float*)d_in[14];
    const float* bb2 = (const float*)d_in[15];
    const float* lng = (const float*)d_in[16];
    const float* lnb = (const float*)d_in[17];
    const float* Wo  = (const float*)d_in[18];
    const float* bo  = (const float*)d_in[19];
    float* out = (float*)d_out;

    float *pv, *kc, *ks, *kv, *gh, *bh;
    cudaGetSymbolAddress((void**)&pv, g_pv);
    cudaGetSymbolAddress((void**)&kc, g_kc);
    cudaGetSymbolAddress((void**)&ks, g_ks);
    cudaGetSymbolAddress((void**)&kv, g_kv);
    cudaGetSymbolAddress((void**)&gh, g_gh);
    cudaGetSymbolAddress((void**)&bh, g_bh);

    __nv_bfloat16 *x3, *Wk3;
    __half *x2, *ln2, *Wpvkv2, *Wg12, *Wb12, *Wo2;
    cudaGetSymbolAddress((void**)&x3,     g_x3);
    cudaGetSymbolAddress((void**)&Wk3,    g_Wk3);
    cudaGetSymbolAddress((void**)&x2,     g_x2);
    cudaGetSymbolAddress((void**)&ln2,    g_ln2);
    cudaGetSymbolAddress((void**)&Wpvkv2, g_Wpvkv2);
    cudaGetSymbolAddress((void**)&Wg12,   g_Wg12);
    cudaGetSymbolAddress((void**)&Wb12,   g_Wb12);
    cudaGetSymbolAddress((void**)&Wo2,    g_Wo2);

    cudaFuncSetAttribute((const void*)gemm_mma<EP_KEY,  false>, cudaFuncAttributeMaxDynamicSharedMemorySize, GEMM_SMEM);
    cudaFuncSetAttribute((const void*)gemm_mma<EP_PVKV, true >, cudaFuncAttributeMaxDynamicSharedMemorySize, GEMM_SMEM);
    cudaFuncSetAttribute((const void*)gemm_mma<EP_GELU, true >, cudaFuncAttributeMaxDynamicSharedMemorySize, GEMM_SMEM);
    cudaFuncSetAttribute((const void*)gemm_mma<EP_OUT,  true >, cudaFuncAttributeMaxDynamicSharedMemorySize, GEMM_SMEM);
    cudaFuncSetAttribute((const void*)gemm_gate, cudaFuncAttributeMaxDynamicSharedMemorySize, GEMM_SMEM);

    // 0-2: activation conversions
    k_cvtA3<<<(MM * DD / 4) / 256, 256>>>(x, x3);
    k_cvtA2<<<(MM * DD / 4) / 256, 256>>>(x, x2);
    k_cvtB3<<<dim3(DD / 32, DD / 32), dim3(32, 8)>>>(Wk, Wk3, DD, DD);
    // 3: key GEMM (bf16 3-product, sensitive path)
    gemm_mma<EP_KEY, false><<<dim3(4, MM / 128), 512, GEMM_SMEM>>>(
        (const uint16_t*)x3, (const uint16_t*)Wk3, bk, nullptr, kc, ks, nullptr, DD, 3 * DD);
    // 4: pv+kv weights (fp16 pairs, packed)
    k_cvtB2<<<dim3(DD / 32, DD / 32), dim3(32, 8)>>>(Wpv, Wpvkv2, DD, DD);
    k_cvtB2<<<dim3(DD / 32, DD / 32), dim3(32, 8)>>>(Wkv, Wpvkv2 + (size_t)DD * 2 * DD, DD, DD);
    // 5: merged pv+kv GEMM (fp16 2-product, N=2048)
    gemm_mma<EP_PVKV, true><<<dim3(8, MM / 128), 512, GEMM_SMEM>>>(
        (const uint16_t*)x2, (const uint16_t*)Wpvkv2, bpv, bkv, pv, kv, nullptr, 2 * DD, 2 * DD);
    // 6-7: gate path (fp16 2-product, virtual concat K''=4096)
    k_cvtB2<<<dim3(DD / 32, 2 * DD / 32), dim3(32, 8)>>>(Wg1, Wg12, 2 * DD, DD);
    gemm_gate<<<dim3(4, MM / 128), 512, GEMM_SMEM>>>((const uint16_t*)x2, (const uint16_t*)Wg12, bg1, gh);
    // 8-9: blend hidden (fp16 2-product)
    k_cvtB2<<<dim3((DD / 2) / 32, DD / 32), dim3(32, 8)>>>(Wb1, Wb12, DD, DD / 2);
    gemm_mma<EP_GELU, true><<<dim3(2, MM / 128), 512, GEMM_SMEM>>>(
        (const uint16_t*)x2, (const uint16_t*)Wb12, bb1, nullptr, bh, nullptr, nullptr, DD / 2, 2 * DD);
    // 10: pos phase cos/sin
    k_sincos<<<(LL * DD) / 256, 256>>>(pp);
    // 11-13: gates / blend softmax / gate cumsum
    k_vg<<<MM / 8, 256>>>(Wg2, bg2);
    k_bw<<<MM / 8, 256>>>(Wb2, bb2);
    k_gatescan<<<BBATCH, 1024>>>();
    // 14-15: scans
    dim3 gscan(DD / 256, NCHUNK, BBATCH);
    k_scanT<<<gscan, 256>>>();
    k_scanC<<<gscan, 256>>>();
    // 16: LayerNorm (fused fp16 pair-split)
    k_ln<<<MM, 256>>>(lng, lnb, ln2);
    // 17-18: output path (fp16 2-product, +residual)
    k_cvtB2<<<dim3(DD / 32, DD / 32), dim3(32, 8)>>>(Wo, Wo2, DD, DD);
    gemm_mma<EP_OUT, true><<<dim3(4, MM / 128), 512, GEMM_SMEM>>>(
        (const uint16_t*)ln2, (const uint16_t*)Wo2, bo, nullptr, out, nullptr, x, DD, 2 * DD);
}